// round 2
// baseline (speedup 1.0000x reference)
#include <cuda_runtime.h>
#include <cstdint>

// Bicubic separable resize, fused vertical+horizontal pass.
// x: (24, 1080, 1920) f32   (B*C flattened)
// w_h: (270, Ph) f32, idx_h: (270, Ph) i32
// w_w: (480, Pw) f32, idx_w: (480, Pw) i32
// out: (24, 270, 480) f32
//
// Each CTA: one (b*c) image plane, R=8 consecutive output rows.
// Phase 1 (vertical): interm[r][w] = sum_p w_h[oh,p] * x[idx_h[oh,p], w]  -> SMEM
// Phase 2 (horizontal): out[oh][ow] = sum_q w_w[ow,q] * interm[r][idx_w[ow,q]]

#define R_TILE 8
#define MAXP 32
#define NTHREADS 512

__global__ __launch_bounds__(NTHREADS, 1)
void bicubic_fused_kernel(const float* __restrict__ x,
                          const float* __restrict__ w_h,
                          const int*   __restrict__ idx_h,
                          const float* __restrict__ w_w,
                          const int*   __restrict__ idx_w,
                          float* __restrict__ out,
                          int H, int W, int OH, int OW,
                          int Ph, int Pw, int nTiles)
{
    extern __shared__ char smemRaw[];
    float* s_ww     = (float*)smemRaw;                 // OW*Pw floats
    int*   s_iw     = (int*)(s_ww + OW * Pw);          // OW*Pw ints
    float* s_interm = (float*)(s_iw + OW * Pw);        // R_TILE*W floats

    __shared__ float s_wv[R_TILE * MAXP];
    __shared__ int   s_iv[R_TILE * MAXP];

    const int tid  = threadIdx.x;
    const int tile = blockIdx.x;
    const int bc   = tile / nTiles;
    const int oh0  = (tile % nTiles) * R_TILE;

    const float* xp = x + (size_t)bc * H * W;

    // --- preload horizontal tables (coalesced) ---
    const int nw = OW * Pw;
    for (int i = tid; i < nw; i += NTHREADS) {
        s_ww[i] = w_w[i];
        s_iw[i] = idx_w[i];
    }
    // --- preload vertical weights for the R_TILE rows of this strip ---
    for (int i = tid; i < R_TILE * Ph; i += NTHREADS) {
        int r = i / Ph, p = i - r * Ph;
        int oh = oh0 + r;
        if (oh < OH) {
            s_wv[r * MAXP + p] = w_h[oh * Ph + p];
            s_iv[r * MAXP + p] = idx_h[oh * Ph + p];
        }
    }
    __syncthreads();

    // --- Phase 1: vertical pass into SMEM ---
    const int totalV = R_TILE * W;
    for (int i = tid; i < totalV; i += NTHREADS) {
        int r = i / W;
        int w = i - r * W;
        int oh = oh0 + r;
        if (oh >= OH) continue;
        float acc = 0.0f;
        const float* wvp = &s_wv[r * MAXP];
        const int*   ivp = &s_iv[r * MAXP];
        #pragma unroll 6
        for (int p = 0; p < Ph; p++) {
            acc += wvp[p] * __ldg(&xp[(size_t)ivp[p] * W + w]);
        }
        s_interm[r * W + w] = acc;
    }
    __syncthreads();

    // --- Phase 2: horizontal pass from SMEM to GMEM ---
    const int totalH = R_TILE * OW;
    float* outp = out + (size_t)bc * OH * OW;
    for (int i = tid; i < totalH; i += NTHREADS) {
        int r  = i / OW;
        int ow = i - r * OW;
        int oh = oh0 + r;
        if (oh >= OH) continue;
        const float* wwp = &s_ww[ow * Pw];
        const int*   iwp = &s_iw[ow * Pw];
        const float* row = &s_interm[r * W];
        float acc = 0.0f;
        #pragma unroll 6
        for (int q = 0; q < Pw; q++) {
            acc += wwp[q] * row[iwp[q]];
        }
        outp[oh * OW + ow] = acc;
    }
}

extern "C" void kernel_launch(void* const* d_in, const int* in_sizes, int n_in,
                              void* d_out, int out_size)
{
    const float* x     = (const float*)d_in[0];
    const float* w_h   = (const float*)d_in[1];
    const int*   idx_h = (const int*)  d_in[2];
    const float* w_w   = (const float*)d_in[3];
    const int*   idx_w = (const int*)  d_in[4];
    float* out = (float*)d_out;

    const int H = 1080, W = 1920, OH = 270, OW = 480;
    const int BC = in_sizes[0] / (H * W);      // 24
    const int Ph = in_sizes[1] / OH;           // ~18
    const int Pw = in_sizes[3] / OW;           // ~18

    const int nTiles = (OH + R_TILE - 1) / R_TILE;   // 34
    size_t smem = (size_t)OW * Pw * 8 + (size_t)R_TILE * W * 4;

    static int attr_set = 0;
    cudaFuncSetAttribute(bicubic_fused_kernel,
                         cudaFuncAttributeMaxDynamicSharedMemorySize,
                         (int)(160 * 1024));
    (void)attr_set;

    dim3 grid(BC * nTiles);
    bicubic_fused_kernel<<<grid, NTHREADS, smem>>>(
        x, w_h, idx_h, w_w, idx_w, out, H, W, OH, OW, Ph, Pw, nTiles);
}

// round 5
// speedup vs baseline: 2.0286x; 2.0286x over previous
#include <cuda_runtime.h>
#include <cstdint>

// Two-pass separable bicubic downscale.
// x: (24, 1080, 1920) f32 -> interm: (24, 270, 1920) f32 -> out: (24, 270, 480) f32
// w_h: (270, Ph) f32, idx_h: (270, Ph) i32
// w_w: (480, Pw) f32, idx_w: (480, Pw) i32

#define H_IN   1080
#define W_IN   1920
#define OH_OUT 270
#define OW_OUT 480
#define BC_MAX 24
#define MAXP   24

// 49.8 MB scratch for the vertical-pass intermediate.
__device__ float g_interm[(size_t)BC_MAX * OH_OUT * W_IN];

// ---------------- Pass 1: vertical ----------------
// grid = BC * OH, block = 480 threads, each thread one float4 (W/4 = 480).
__global__ __launch_bounds__(480)
void bicubic_vpass(const float* __restrict__ x,
                   const float* __restrict__ w_h,
                   const int*   __restrict__ idx_h,
                   int BC, int Ph)
{
    const int row = blockIdx.x;            // row in [0, BC*OH)
    const int oh  = row % OH_OUT;
    const int bc  = row / OH_OUT;
    const int t   = threadIdx.x;           // 0..479 -> float4 column

    // Per-row taps (same address across all lanes -> broadcast, L1-hot).
    float wv[MAXP];
    int   rv[MAXP];
    #pragma unroll 6
    for (int p = 0; p < Ph; p++) {
        wv[p] = __ldg(&w_h[oh * Ph + p]);
        rv[p] = __ldg(&idx_h[oh * Ph + p]);
    }

    const float4* xp = (const float4*)(x + (size_t)bc * H_IN * W_IN);

    float4 acc = make_float4(0.f, 0.f, 0.f, 0.f);
    #pragma unroll 6
    for (int p = 0; p < Ph; p++) {
        float4 v = __ldg(&xp[(size_t)rv[p] * (W_IN / 4) + t]);
        float w = wv[p];
        acc.x += w * v.x;
        acc.y += w * v.y;
        acc.z += w * v.z;
        acc.w += w * v.w;
    }

    float4* ip = (float4*)(g_interm + (size_t)row * W_IN);
    ip[t] = acc;
}

// ---------------- Pass 2: horizontal ----------------
// grid = BC * OH, block = 480 threads, each thread one output pixel.
__global__ __launch_bounds__(480)
void bicubic_hpass(const float* __restrict__ w_w,
                   const int*   __restrict__ idx_w,
                   float* __restrict__ out,
                   int BC, int Pw)
{
    __shared__ float s_row[W_IN];

    const int row = blockIdx.x;            // (bc, oh) flattened
    const int ow  = threadIdx.x;           // 0..479

    // Stage the interm row into smem, coalesced float4.
    const float4* ip = (const float4*)(g_interm + (size_t)row * W_IN);
    ((float4*)s_row)[ow] = ip[ow];

    // Per-output-pixel taps (contiguous per thread, L1-hot across CTAs).
    float wq[MAXP];
    int   iq[MAXP];
    #pragma unroll 6
    for (int q = 0; q < Pw; q++) {
        wq[q] = __ldg(&w_w[ow * Pw + q]);
        iq[q] = __ldg(&idx_w[ow * Pw + q]);
    }

    __syncthreads();

    float acc = 0.f;
    #pragma unroll 6
    for (int q = 0; q < Pw; q++) {
        acc += wq[q] * s_row[iq[q]];
    }

    out[(size_t)row * OW_OUT + ow] = acc;
}

extern "C" void kernel_launch(void* const* d_in, const int* in_sizes, int n_in,
                              void* d_out, int out_size)
{
    const float* x     = (const float*)d_in[0];
    const float* w_h   = (const float*)d_in[1];
    const int*   idx_h = (const int*)  d_in[2];
    const float* w_w   = (const float*)d_in[3];
    const int*   idx_w = (const int*)  d_in[4];
    float* out = (float*)d_out;

    const int BC = in_sizes[0] / (H_IN * W_IN);   // 24
    const int Ph = in_sizes[1] / OH_OUT;          // ~18
    const int Pw = in_sizes[3] / OW_OUT;          // ~18

    dim3 grid(BC * OH_OUT);                       // 6480
    bicubic_vpass<<<grid, 480>>>(x, w_h, idx_h, BC, Ph);
    bicubic_hpass<<<grid, 480>>>(w_w, idx_w, out, BC, Pw);
}

// round 8
// speedup vs baseline: 4.8366x; 2.3842x over previous
#include <cuda_runtime.h>
#include <cstdint>

// Fused separable bicubic downscale, one kernel.
// x: (24, 1080, 1920) f32 -> out: (24, 270, 480) f32
// w_h: (270, Ph) f32, idx_h: (270, Ph) i32   (Ph <= 18)
// w_w: (480, Pw) f32, idx_w: (480, Pw) i32   (Pw <= 18)
//
// CTA = (bc, strip of R_TILE output rows). 480 threads.
// Phase V: thread t computes float4 column t of the vertically-filtered strip,
//          stores into smem in a 4-way partitioned layout (kills LDS conflicts).
// Phase H: thread t = output column ow=t, taps held in registers (loaded once,
//          amortized over R_TILE rows).

#define H_IN   1080
#define W_IN   1920
#define OH_OUT 270
#define OW_OUT 480
#define R_TILE 6
#define MAXP   18
#define NT     480

__global__ __launch_bounds__(NT, 2)
void bicubic_fused2(const float* __restrict__ x,
                    const float* __restrict__ w_h,
                    const int*   __restrict__ idx_h,
                    const float* __restrict__ w_w,
                    const int*   __restrict__ idx_w,
                    float* __restrict__ out,
                    int BC, int Ph, int Pw, int nTiles)
{
    extern __shared__ float s_interm[];          // R_TILE * 1920, partitioned
    __shared__ float s_wv[R_TILE * MAXP];
    __shared__ int   s_iv[R_TILE * MAXP];

    const int tid = threadIdx.x;
    const int bc  = blockIdx.x / nTiles;
    const int oh0 = (blockIdx.x % nTiles) * R_TILE;
    const int nr  = min(R_TILE, OH_OUT - oh0);

    // ---- vertical tables -> smem (coalesced, tiny) ----
    for (int i = tid; i < nr * Ph; i += NT) {
        int r = i / Ph, p = i - r * Ph;
        s_wv[r * MAXP + p] = w_h[(oh0 + r) * Ph + p];
        s_iv[r * MAXP + p] = idx_h[(oh0 + r) * Ph + p];
    }

    // ---- horizontal taps -> registers (once per CTA, amortized over nr rows) ----
    const int ow = tid;                          // 0..479
    float wq[MAXP];
    int   iqT[MAXP];                             // partition-transformed index
    #pragma unroll 6
    for (int q = 0; q < Pw; q++) {
        wq[q] = __ldg(&w_w[ow * Pw + q]);
        int iq = __ldg(&idx_w[ow * Pw + q]);
        iqT[q] = (iq & 3) * (W_IN / 4) + (iq >> 2);
    }

    __syncthreads();

    // ---- Phase V: vertical filter, float4 per thread, store partitioned ----
    const float4* xp = (const float4*)(x + (size_t)bc * H_IN * W_IN);
    for (int r = 0; r < nr; r++) {
        float4 acc = make_float4(0.f, 0.f, 0.f, 0.f);
        const float* wvp = &s_wv[r * MAXP];
        const int*   ivp = &s_iv[r * MAXP];
        #pragma unroll 6
        for (int p = 0; p < Ph; p++) {
            float w = wvp[p];
            float4 v = __ldg(&xp[(size_t)ivp[p] * (W_IN / 4) + tid]);
            acc.x += w * v.x;
            acc.y += w * v.y;
            acc.z += w * v.z;
            acc.w += w * v.w;
        }
        // column c = 4*tid + j  ->  s[(c&3)*480 + (c>>2)] = s[j*480 + tid]
        float* sd = s_interm + r * W_IN;
        sd[0 * (W_IN / 4) + tid] = acc.x;
        sd[1 * (W_IN / 4) + tid] = acc.y;
        sd[2 * (W_IN / 4) + tid] = acc.z;
        sd[3 * (W_IN / 4) + tid] = acc.w;
    }

    __syncthreads();

    // ---- Phase H: conflict-free smem gather, taps from registers ----
    float* outp = out + ((size_t)bc * OH_OUT + oh0) * OW_OUT;
    for (int r = 0; r < nr; r++) {
        const float* srow = s_interm + r * W_IN;
        float acc = 0.f;
        #pragma unroll 6
        for (int q = 0; q < Pw; q++) {
            acc += wq[q] * srow[iqT[q]];
        }
        outp[r * OW_OUT + ow] = acc;
    }
}

extern "C" void kernel_launch(void* const* d_in, const int* in_sizes, int n_in,
                              void* d_out, int out_size)
{
    const float* x     = (const float*)d_in[0];
    const float* w_h   = (const float*)d_in[1];
    const int*   idx_h = (const int*)  d_in[2];
    const float* w_w   = (const float*)d_in[3];
    const int*   idx_w = (const int*)  d_in[4];
    float* out = (float*)d_out;

    const int BC = in_sizes[0] / (H_IN * W_IN);   // 24
    const int Ph = in_sizes[1] / OH_OUT;          // <= 18
    const int Pw = in_sizes[3] / OW_OUT;          // <= 18

    const int nTiles = (OH_OUT + R_TILE - 1) / R_TILE;   // 45
    size_t smem = (size_t)R_TILE * W_IN * sizeof(float); // 46 KB

    cudaFuncSetAttribute(bicubic_fused2,
                         cudaFuncAttributeMaxDynamicSharedMemorySize,
                         (int)(64 * 1024));

    dim3 grid(BC * nTiles);                       // 1080
    bicubic_fused2<<<grid, NT, smem>>>(
        x, w_h, idx_h, w_w, idx_w, out, BC, Ph, Pw, nTiles);
}

// round 9
// speedup vs baseline: 5.5999x; 1.1578x over previous
#include <cuda_runtime.h>
#include <cstdint>

// Fused separable bicubic downscale, scatter-vertical formulation.
// x: (24, 1080, 1920) f32 -> out: (24, 270, 480) f32
// w_h: (270, Ph) f32, idx_h: (270, Ph) i32   (Ph <= 18)
// w_w: (480, Pw) f32, idx_w: (480, Pw) i32   (Pw <= 18)
//
// CTA = (bc, strip of R_TILE=6 output rows), 480 threads, thread t = float4 col.
// Build: w_acc[i - i0][r] = sum of vertical weights mapping input row i to
//        strip output row r (dense table in smem, atomicAdd for mirror dups).
// Phase V: sweep each unique input row ONCE, scatter-FMA into 6 float4 accs.
// Phase H: taps in registers, conflict-free partitioned smem gather.

#define H_IN     1080
#define W_IN     1920
#define OH_OUT   270
#define OW_OUT   480
#define R_TILE   6
#define MAXP     18
#define NT       480
#define SPAN_MAX 64      // interior span = 4*(R_TILE-1) + Ph = 38; 64 is safe
#define RPAD     8       // w_acc row stride (pad 6 -> 8 for LDS.128)

__global__ __launch_bounds__(NT, 2)
void bicubic_fused3(const float* __restrict__ x,
                    const float* __restrict__ w_h,
                    const int*   __restrict__ idx_h,
                    const float* __restrict__ w_w,
                    const int*   __restrict__ idx_w,
                    float* __restrict__ out,
                    int Ph, int Pw, int nTiles)
{
    extern __shared__ float s_interm[];                // R_TILE * 1920 floats
    __shared__ float s_wacc[SPAN_MAX * RPAD];          // [span][RPAD]
    __shared__ int   s_imin, s_imax;

    const int tid = threadIdx.x;
    const int bc  = blockIdx.x / nTiles;
    const int oh0 = (blockIdx.x % nTiles) * R_TILE;    // OH % R_TILE == 0

    // ---- init build structures ----
    if (tid == 0) { s_imin = 0x7fffffff; s_imax = 0; }
    for (int i = tid; i < SPAN_MAX * RPAD; i += NT) s_wacc[i] = 0.f;
    __syncthreads();

    // ---- find index span of this strip ----
    const int nTaps = R_TILE * Ph;                     // 108
    for (int i = tid; i < nTaps; i += NT) {
        int r = i / Ph, p = i - r * Ph;
        int iv = idx_h[(oh0 + r) * Ph + p];
        atomicMin(&s_imin, iv);
        atomicMax(&s_imax, iv);
    }
    __syncthreads();
    const int i0   = s_imin;
    const int span = s_imax - i0 + 1;                  // <= 38 typ.

    // ---- build dense contribution table (atomicAdd: mirrored dup taps) ----
    for (int i = tid; i < nTaps; i += NT) {
        int r = i / Ph, p = i - r * Ph;
        int   iv = idx_h[(oh0 + r) * Ph + p];
        float wv = w_h[(oh0 + r) * Ph + p];
        atomicAdd(&s_wacc[(iv - i0) * RPAD + r], wv);
    }
    __syncthreads();

    // ---- Phase V: one pass over unique input rows, scatter into 6 accs ----
    const float4* xp = (const float4*)(x + (size_t)bc * H_IN * W_IN)
                     + (size_t)i0 * (W_IN / 4) + tid;
    float4 acc[R_TILE];
    #pragma unroll
    for (int r = 0; r < R_TILE; r++) acc[r] = make_float4(0.f, 0.f, 0.f, 0.f);

    for (int i = 0; i < span; i++) {
        float4 v = __ldg(xp + (size_t)i * (W_IN / 4));
        // two LDS.128 broadcasts fetch all 6 weights for this input row
        float4 w03 = *(const float4*)&s_wacc[i * RPAD + 0];
        float4 w47 = *(const float4*)&s_wacc[i * RPAD + 4];
        float wr[R_TILE] = { w03.x, w03.y, w03.z, w03.w, w47.x, w47.y };
        #pragma unroll
        for (int r = 0; r < R_TILE; r++) {
            acc[r].x += wr[r] * v.x;
            acc[r].y += wr[r] * v.y;
            acc[r].z += wr[r] * v.z;
            acc[r].w += wr[r] * v.w;
        }
    }

    // store partitioned: column c = 4*tid + j -> s[j*480 + tid]
    #pragma unroll
    for (int r = 0; r < R_TILE; r++) {
        float* sd = s_interm + r * W_IN;
        sd[0 * (W_IN / 4) + tid] = acc[r].x;
        sd[1 * (W_IN / 4) + tid] = acc[r].y;
        sd[2 * (W_IN / 4) + tid] = acc[r].z;
        sd[3 * (W_IN / 4) + tid] = acc[r].w;
    }
    __syncthreads();

    // ---- Phase H: taps in registers, conflict-free smem gather ----
    const int ow = tid;
    float wq[MAXP];
    int   iqT[MAXP];
    #pragma unroll 6
    for (int q = 0; q < Pw; q++) {
        wq[q] = __ldg(&w_w[ow * Pw + q]);
        int iq = __ldg(&idx_w[ow * Pw + q]);
        iqT[q] = (iq & 3) * (W_IN / 4) + (iq >> 2);
    }

    float* outp = out + ((size_t)bc * OH_OUT + oh0) * OW_OUT + ow;
    #pragma unroll
    for (int r = 0; r < R_TILE; r++) {
        const float* srow = s_interm + r * W_IN;
        float a = 0.f;
        #pragma unroll 6
        for (int q = 0; q < Pw; q++) {
            a += wq[q] * srow[iqT[q]];
        }
        outp[r * OW_OUT] = a;
    }
}

extern "C" void kernel_launch(void* const* d_in, const int* in_sizes, int n_in,
                              void* d_out, int out_size)
{
    const float* x     = (const float*)d_in[0];
    const float* w_h   = (const float*)d_in[1];
    const int*   idx_h = (const int*)  d_in[2];
    const float* w_w   = (const float*)d_in[3];
    const int*   idx_w = (const int*)  d_in[4];
    float* out = (float*)d_out;

    const int BC = in_sizes[0] / (H_IN * W_IN);   // 24
    const int Ph = in_sizes[1] / OH_OUT;          // <= 18
    const int Pw = in_sizes[3] / OW_OUT;          // <= 18

    const int nTiles = OH_OUT / R_TILE;           // 45
    size_t smem = (size_t)R_TILE * W_IN * sizeof(float); // 46 KB

    cudaFuncSetAttribute(bicubic_fused3,
                         cudaFuncAttributeMaxDynamicSharedMemorySize,
                         (int)(64 * 1024));

    dim3 grid(BC * nTiles);                       // 1080
    bicubic_fused3<<<grid, NT, smem>>>(
        x, w_h, idx_h, w_w, idx_w, out, Ph, Pw, nTiles);
}